// round 1
// baseline (speedup 1.0000x reference)
#include <cuda_runtime.h>
#include <cstdint>

// Problem constants
// x: (B=8, H=256, W=256, C=64) fp32, WIN=16, half=8
// out: (B, 961, 16*16*64) fp32, partition order (0,0),(0,8),(8,0),(8,8)
// windows per partition: 256, 240, 240, 225  -> 961 per batch
//
// Each window-row (16 cols * 64 ch = 1024 floats = 4KB) is contiguous in both
// input and output => batched 4KB memcpy. One block per window, 256 threads,
// one float4 per thread per row, 16 rows unrolled.

#define Hh 256
#define Ww 256
#define Cc 64
#define NPB 961           // windows per batch
#define ROW_F4 (Ww * Cc / 4)   // float4 per input image row = 4096

__global__ void __launch_bounds__(256, 8)
partition_kernel(const float* __restrict__ x, float* __restrict__ out)
{
    const int blk = blockIdx.x;            // b * 961 + p
    const int b   = blk / NPB;
    const int p   = blk - b * NPB;

    int r0, c0, nc, base;
    if (p < 256)      { r0 = 0; c0 = 0; nc = 16; base = 0;   }
    else if (p < 496) { r0 = 0; c0 = 8; nc = 15; base = 256; }
    else if (p < 736) { r0 = 8; c0 = 0; nc = 16; base = 496; }
    else              { r0 = 8; c0 = 8; nc = 15; base = 736; }

    const int q  = p - base;
    const int wr = q / nc;
    const int wc = q - wr * nc;
    const int row0 = r0 + wr * 16;
    const int col0 = c0 + wc * 16;

    // float4 base pointers
    const float4* __restrict__ src =
        reinterpret_cast<const float4*>(x) +
        (size_t)(b * Hh + row0) * ROW_F4 + (size_t)col0 * (Cc / 4);
    float4* __restrict__ dst =
        reinterpret_cast<float4*>(out) + (size_t)blk * (16 * 16 * Cc / 4);

    const int t = threadIdx.x;             // 0..255: one float4 of the 4KB row

    // 16 window rows; each row: 256 float4 contiguous on both sides.
    // Unrolled so ptxas front-batches the independent LDG.128s (high MLP).
    float4 v[16];
#pragma unroll
    for (int i = 0; i < 16; ++i)
        v[i] = src[(size_t)i * ROW_F4 + t];
#pragma unroll
    for (int i = 0; i < 16; ++i)
        dst[i * 256 + t] = v[i];
}

extern "C" void kernel_launch(void* const* d_in, const int* in_sizes, int n_in,
                              void* d_out, int out_size)
{
    const float* x = (const float*)d_in[0];
    float* out = (float*)d_out;
    const int nblocks = 8 * NPB;           // 7688
    partition_kernel<<<nblocks, 256>>>(x, out);
}

// round 2
// speedup vs baseline: 1.1163x; 1.1163x over previous
#include <cuda_runtime.h>
#include <cstdint>

// x: (B=8, H=256, W=256, C=64) fp32, WIN=16, half=8
// out: (B, 961, 16*16*64) fp32, partition order (0,0),(0,8),(8,0),(8,8)
// windows per partition: 256, 240, 240, 225  -> 961 per batch
//
// Each window-row (16 cols * 64 ch = 1024 floats = 4KB) is contiguous in both
// input and output => batched 4KB copies. One block per window, 256 threads,
// one float4 per thread per row, all 16 rows loaded before any store
// (min-2-blocks launch bound -> ~128 regs, true 16-deep MLP).
// Streaming stores (__stcs) keep the reused input slice resident in L2.

#define Hh 256
#define Ww 256
#define Cc 64
#define NPB 961                // windows per batch
#define ROW_F4 (Ww * Cc / 4)   // float4 per input image row = 4096

__global__ void __launch_bounds__(256, 2)
partition_kernel(const float* __restrict__ x, float* __restrict__ out)
{
    const int blk = blockIdx.x;            // b * 961 + p
    const int b   = blk / NPB;
    const int p   = blk - b * NPB;

    int r0, c0, nc, base;
    if (p < 256)      { r0 = 0; c0 = 0; nc = 16; base = 0;   }
    else if (p < 496) { r0 = 0; c0 = 8; nc = 15; base = 256; }
    else if (p < 736) { r0 = 8; c0 = 0; nc = 16; base = 496; }
    else              { r0 = 8; c0 = 8; nc = 15; base = 736; }

    const int q  = p - base;
    const int wr = q / nc;
    const int wc = q - wr * nc;
    const int row0 = r0 + wr * 16;
    const int col0 = c0 + wc * 16;

    const float4* __restrict__ src =
        reinterpret_cast<const float4*>(x) +
        (size_t)(b * Hh + row0) * ROW_F4 + (size_t)col0 * (Cc / 4);
    float4* __restrict__ dst =
        reinterpret_cast<float4*>(out) + (size_t)blk * (16 * 16 * Cc / 4);

    const int t = threadIdx.x;             // 0..255: one float4 of the 4KB row

    // Front-batch ALL 16 independent LDG.128s (64 result regs live at once),
    // then drain with 16 streaming STG.128s.
    float4 v[16];
#pragma unroll
    for (int i = 0; i < 16; ++i)
        v[i] = __ldg(&src[(size_t)i * ROW_F4 + t]);
#pragma unroll
    for (int i = 0; i < 16; ++i)
        __stcs(&dst[i * 256 + t], v[i]);
}

extern "C" void kernel_launch(void* const* d_in, const int* in_sizes, int n_in,
                              void* d_out, int out_size)
{
    const float* x = (const float*)d_in[0];
    float* out = (float*)d_out;
    const int nblocks = 8 * NPB;           // 7688
    partition_kernel<<<nblocks, 256>>>(x, out);
}